// round 1
// baseline (speedup 1.0000x reference)
#include <cuda_runtime.h>
#include <math.h>

// Problem constants
#define BWIN   4096          // B_ windows
#define NTOK   49            // tokens per window
#define CDIM   384           // embed dim
#define NHEAD  12
#define HD     32            // head dim
#define NWMASK 64            // windows per image (mask dim 0)
#define TOKENS (BWIN * NTOK) // 200704

#define QKV_COLS (3 * CDIM)  // 1152

// Scratch (static device globals; allocation-free per harness rules)
__device__ float g_q[(size_t)BWIN * NHEAD * NTOK * HD];   // (b,h,n,d)
__device__ float g_k[(size_t)BWIN * NHEAD * NTOK * HD];
__device__ float g_v[(size_t)BWIN * NHEAD * NTOK * HD];
__device__ float g_ctx[(size_t)TOKENS * CDIM];            // (t, h*32+d)

// ---------------------------------------------------------------------------
// GEMM 1: qkv = x @ qkv_w^T + qkv_b, scattered to q/k/v scratch.
// A: x [TOKENS, 384] row-major. B: qkv_w [1152, 384] row-major (K inner).
// 64x64 tile, 256 threads, 4x4 per thread, K-chunk 16.
// TOKENS % 64 == 0, 1152 % 64 == 0, 384 % 16 == 0: no bounds checks needed.
// ---------------------------------------------------------------------------
__global__ __launch_bounds__(256) void qkv_gemm_kernel(
    const float* __restrict__ x,
    const float* __restrict__ w,
    const float* __restrict__ bias)
{
    __shared__ __align__(16) float As[16][68];
    __shared__ __align__(16) float Bs[16][68];

    const int tid = threadIdx.x;
    const int tx = tid & 15;          // 0..15
    const int ty = tid >> 4;          // 0..15
    const int m0 = blockIdx.x * 64;
    const int n0 = blockIdx.y * 64;

    const int lrow = tid >> 2;        // 0..63
    const int lk4  = (tid & 3) * 4;   // 0,4,8,12

    float acc[4][4];
#pragma unroll
    for (int i = 0; i < 4; i++)
#pragma unroll
        for (int j = 0; j < 4; j++) acc[i][j] = 0.f;

    for (int k0 = 0; k0 < CDIM; k0 += 16) {
        float4 av = *(const float4*)&x[(size_t)(m0 + lrow) * CDIM + k0 + lk4];
        float4 bv = *(const float4*)&w[(size_t)(n0 + lrow) * CDIM + k0 + lk4];
        As[lk4 + 0][lrow] = av.x; As[lk4 + 1][lrow] = av.y;
        As[lk4 + 2][lrow] = av.z; As[lk4 + 3][lrow] = av.w;
        Bs[lk4 + 0][lrow] = bv.x; Bs[lk4 + 1][lrow] = bv.y;
        Bs[lk4 + 2][lrow] = bv.z; Bs[lk4 + 3][lrow] = bv.w;
        __syncthreads();
#pragma unroll
        for (int kk = 0; kk < 16; kk++) {
            float4 a = *(const float4*)&As[kk][ty * 4];
            float4 b = *(const float4*)&Bs[kk][tx * 4];
            float ar[4] = {a.x, a.y, a.z, a.w};
            float br[4] = {b.x, b.y, b.z, b.w};
#pragma unroll
            for (int i = 0; i < 4; i++)
#pragma unroll
                for (int j = 0; j < 4; j++) acc[i][j] += ar[i] * br[j];
        }
        __syncthreads();
    }

    const float qscale = 0.17677669529663687f;  // 32^-0.5

#pragma unroll
    for (int i = 0; i < 4; i++) {
        const int t = m0 + ty * 4 + i;
        const int b = t / NTOK;
        const int n = t - b * NTOK;
#pragma unroll
        for (int j = 0; j < 4; j++) {
            const int c = n0 + tx * 4 + j;
            float val = acc[i][j] + bias[c];
            const int three = c / CDIM;
            const int rem = c - three * CDIM;
            const int h = rem >> 5;          // /32
            const int d = rem & 31;
            const size_t off = (((size_t)b * NHEAD + h) * NTOK + n) * HD + d;
            if (three == 0)      g_q[off] = val * qscale;
            else if (three == 1) g_k[off] = val;
            else                 g_v[off] = val;
        }
    }
}

// ---------------------------------------------------------------------------
// Attention: one block per (window, head). 256 threads.
// scores = qk^T + bias(head) + mask(window), softmax, out = attn @ v.
// ---------------------------------------------------------------------------
__global__ __launch_bounds__(256) void attn_kernel(
    const float* __restrict__ mask,
    const float* __restrict__ bias_table,
    const int*   __restrict__ rel_index)
{
    const int bh = blockIdx.x;
    const int b = bh / NHEAD;
    const int h = bh - b * NHEAD;
    const int wmask = b & (NWMASK - 1);   // b % 64

    __shared__ float qs[NTOK * 33];
    __shared__ float ks[NTOK * 33];
    __shared__ float vs[NTOK * 33];
    __shared__ float s[NTOK * 50];

    const float* __restrict__ qg = g_q + (size_t)bh * NTOK * HD;
    const float* __restrict__ kg = g_k + (size_t)bh * NTOK * HD;
    const float* __restrict__ vg = g_v + (size_t)bh * NTOK * HD;

    for (int idx = threadIdx.x; idx < NTOK * HD; idx += 256) {
        const int n = idx >> 5;
        const int d = idx & 31;
        qs[n * 33 + d] = qg[idx];
        ks[n * 33 + d] = kg[idx];
        vs[n * 33 + d] = vg[idx];
    }
    __syncthreads();

    // scores
    for (int idx = threadIdx.x; idx < NTOK * NTOK; idx += 256) {
        const int i = idx / NTOK;
        const int j = idx - i * NTOK;
        float a = 0.f;
#pragma unroll
        for (int m = 0; m < HD; m++) a += qs[i * 33 + m] * ks[j * 33 + m];
        a += bias_table[rel_index[idx] * NHEAD + h];
        a += mask[((size_t)wmask * NTOK + i) * NTOK + j];
        s[i * 50 + j] = a;
    }
    __syncthreads();

    // softmax, one warp per row
    const int warp = threadIdx.x >> 5;
    const int lane = threadIdx.x & 31;
    for (int i = warp; i < NTOK; i += 8) {
        float v0 = s[i * 50 + lane];
        float v1 = (lane < NTOK - 32) ? s[i * 50 + lane + 32] : -INFINITY;
        float mx = fmaxf(v0, v1);
#pragma unroll
        for (int o = 16; o > 0; o >>= 1)
            mx = fmaxf(mx, __shfl_xor_sync(0xFFFFFFFFu, mx, o));
        float e0 = __expf(v0 - mx);
        float e1 = (lane < NTOK - 32) ? __expf(v1 - mx) : 0.f;
        float sum = e0 + e1;
#pragma unroll
        for (int o = 16; o > 0; o >>= 1)
            sum += __shfl_xor_sync(0xFFFFFFFFu, sum, o);
        const float inv = 1.f / sum;
        s[i * 50 + lane] = e0 * inv;
        if (lane < NTOK - 32) s[i * 50 + lane + 32] = e1 * inv;
    }
    __syncthreads();

    // out = attn @ v  -> ctx layout (t, h*32+d)
    for (int idx = threadIdx.x; idx < NTOK * HD; idx += 256) {
        const int i = idx >> 5;
        const int d = idx & 31;
        float a = 0.f;
#pragma unroll
        for (int j = 0; j < NTOK; j++) a += s[i * 50 + j] * vs[j * 33 + d];
        g_ctx[((size_t)b * NTOK + i) * CDIM + h * HD + d] = a;
    }
}

// ---------------------------------------------------------------------------
// GEMM 2: out = ctx @ proj_w^T + proj_b. Same tiling as GEMM 1.
// ---------------------------------------------------------------------------
__global__ __launch_bounds__(256) void proj_gemm_kernel(
    const float* __restrict__ w,
    const float* __restrict__ bias,
    float* __restrict__ out)
{
    __shared__ __align__(16) float As[16][68];
    __shared__ __align__(16) float Bs[16][68];

    const int tid = threadIdx.x;
    const int tx = tid & 15;
    const int ty = tid >> 4;
    const int m0 = blockIdx.x * 64;
    const int n0 = blockIdx.y * 64;

    const int lrow = tid >> 2;
    const int lk4  = (tid & 3) * 4;

    float acc[4][4];
#pragma unroll
    for (int i = 0; i < 4; i++)
#pragma unroll
        for (int j = 0; j < 4; j++) acc[i][j] = 0.f;

    for (int k0 = 0; k0 < CDIM; k0 += 16) {
        float4 av = *(const float4*)&g_ctx[(size_t)(m0 + lrow) * CDIM + k0 + lk4];
        float4 bv = *(const float4*)&w[(size_t)(n0 + lrow) * CDIM + k0 + lk4];
        As[lk4 + 0][lrow] = av.x; As[lk4 + 1][lrow] = av.y;
        As[lk4 + 2][lrow] = av.z; As[lk4 + 3][lrow] = av.w;
        Bs[lk4 + 0][lrow] = bv.x; Bs[lk4 + 1][lrow] = bv.y;
        Bs[lk4 + 2][lrow] = bv.z; Bs[lk4 + 3][lrow] = bv.w;
        __syncthreads();
#pragma unroll
        for (int kk = 0; kk < 16; kk++) {
            float4 a = *(const float4*)&As[kk][ty * 4];
            float4 b = *(const float4*)&Bs[kk][tx * 4];
            float ar[4] = {a.x, a.y, a.z, a.w};
            float br[4] = {b.x, b.y, b.z, b.w};
#pragma unroll
            for (int i = 0; i < 4; i++)
#pragma unroll
                for (int j = 0; j < 4; j++) acc[i][j] += ar[i] * br[j];
        }
        __syncthreads();
    }

#pragma unroll
    for (int i = 0; i < 4; i++) {
        const int t = m0 + ty * 4 + i;
#pragma unroll
        for (int j = 0; j < 4; j++) {
            const int c = n0 + tx * 4 + j;
            out[(size_t)t * CDIM + c] = acc[i][j] + bias[c];
        }
    }
}

// ---------------------------------------------------------------------------
// Inputs (metadata order):
// 0: x          (4096, 49, 384) f32
// 1: mask       (64, 49, 49)    f32
// 2: qkv_w      (1152, 384)     f32
// 3: qkv_b      (1152,)         f32
// 4: proj_w     (384, 384)      f32
// 5: proj_b     (384,)          f32
// 6: bias_table (169, 12)       f32
// 7: rel_index  (49, 49)        i32
// out: (4096, 49, 384) f32
// ---------------------------------------------------------------------------
extern "C" void kernel_launch(void* const* d_in, const int* in_sizes, int n_in,
                              void* d_out, int out_size)
{
    const float* x          = (const float*)d_in[0];
    const float* mask       = (const float*)d_in[1];
    const float* qkv_w      = (const float*)d_in[2];
    const float* qkv_b      = (const float*)d_in[3];
    const float* proj_w     = (const float*)d_in[4];
    const float* proj_b     = (const float*)d_in[5];
    const float* bias_table = (const float*)d_in[6];
    const int*   rel_index  = (const int*)d_in[7];
    float* out = (float*)d_out;

    dim3 g1(TOKENS / 64, QKV_COLS / 64);   // 3136 x 18
    qkv_gemm_kernel<<<g1, 256>>>(x, qkv_w, qkv_b);

    attn_kernel<<<BWIN * NHEAD, 256>>>(mask, bias_table, rel_index);

    dim3 g2(TOKENS / 64, CDIM / 64);       // 3136 x 6
    proj_gemm_kernel<<<g2, 256>>>(proj_w, proj_b, out);
}

// round 5
// speedup vs baseline: 1.8880x; 1.8880x over previous
#include <cuda_runtime.h>
#include <cuda_bf16.h>
#include <math.h>
#include <stdint.h>

// ---------------------------------------------------------------------------
// Problem constants
// ---------------------------------------------------------------------------
#define BWIN   4096
#define NTOK   49
#define CDIM   384
#define NHEAD  12
#define HD     32
#define NWMASK 64
#define TOKENS (BWIN * NTOK)   // 200704
#define QKV_COLS (3 * CDIM)    // 1152

// Scratch
__device__ float g_q[(size_t)BWIN * NHEAD * NTOK * HD];
__device__ float g_k[(size_t)BWIN * NHEAD * NTOK * HD];
__device__ float g_v[(size_t)BWIN * NHEAD * NTOK * HD];
__device__ float g_ctx[(size_t)TOKENS * CDIM];

// ---------------------------------------------------------------------------
// helpers
// ---------------------------------------------------------------------------
__device__ __forceinline__ uint32_t smem_to_u32(const void* smem_ptr) {
    uint32_t addr;
    asm("{ .reg .u64 tmp; cvta.to.shared.u64 tmp, %1; cvt.u32.u64 %0, tmp; }"
        : "=r"(addr) : "l"(smem_ptr));
    return addr;
}

__device__ __forceinline__ uint32_t lds_u32(uint32_t addr) {
    uint32_t v;
    asm volatile("ld.shared.b32 %0, [%1];" : "=r"(v) : "r"(addr));
    return v;
}

__device__ __forceinline__ void mma_bf16(float c[4], const uint32_t a[4],
                                         uint32_t b0, uint32_t b1) {
    asm volatile(
        "mma.sync.aligned.m16n8k16.row.col.f32.bf16.bf16.f32 "
        "{%0,%1,%2,%3}, {%4,%5,%6,%7}, {%8,%9}, {%0,%1,%2,%3};"
        : "+f"(c[0]), "+f"(c[1]), "+f"(c[2]), "+f"(c[3])
        : "r"(a[0]), "r"(a[1]), "r"(a[2]), "r"(a[3]), "r"(b0), "r"(b1));
}

// split fp32x4 into hi/lo bf16x4, store 8B each
__device__ __forceinline__ void split_sts(float4 a, uint32_t hi_addr, uint32_t lo_addr)
{
    __nv_bfloat16 h0 = __float2bfloat16(a.x);
    __nv_bfloat16 h1 = __float2bfloat16(a.y);
    __nv_bfloat16 h2 = __float2bfloat16(a.z);
    __nv_bfloat16 h3 = __float2bfloat16(a.w);
    __nv_bfloat16 l0 = __float2bfloat16(a.x - __bfloat162float(h0));
    __nv_bfloat16 l1 = __float2bfloat16(a.y - __bfloat162float(h1));
    __nv_bfloat16 l2 = __float2bfloat16(a.z - __bfloat162float(h2));
    __nv_bfloat16 l3 = __float2bfloat16(a.w - __bfloat162float(h3));
    uint32_t hx = (uint32_t)__bfloat16_as_ushort(h0) | ((uint32_t)__bfloat16_as_ushort(h1) << 16);
    uint32_t hy = (uint32_t)__bfloat16_as_ushort(h2) | ((uint32_t)__bfloat16_as_ushort(h3) << 16);
    uint32_t lx = (uint32_t)__bfloat16_as_ushort(l0) | ((uint32_t)__bfloat16_as_ushort(l1) << 16);
    uint32_t ly = (uint32_t)__bfloat16_as_ushort(l2) | ((uint32_t)__bfloat16_as_ushort(l3) << 16);
    asm volatile("st.shared.v2.u32 [%0], {%1, %2};" :: "r"(hi_addr), "r"(hx), "r"(hy) : "memory");
    asm volatile("st.shared.v2.u32 [%0], {%1, %2};" :: "r"(lo_addr), "r"(lx), "r"(ly) : "memory");
}

// ---------------------------------------------------------------------------
// GEMM config: CTA tile 128(M) x 64(N), K chunks of 32, double-buffered smem.
// 8 warps: wm = wid&1 (M 64 each), wn = wid>>1 (N 16 each). Warp tile 64x16.
// Smem rows padded to 40 bf16 (80B): conflict-free fragment loads.
// ---------------------------------------------------------------------------
#define TM 128
#define TN 64
#define KCH 32
#define NCH (CDIM / KCH)            // 12
#define ROWSTR 40
#define A_HALF (TM * ROWSTR * 2)    // 10240
#define B_HALF (TN * ROWSTR * 2)    // 5120
#define STAGE (2 * A_HALF + 2 * B_HALF)  // 30720
#define GEMM_SMEM (2 * STAGE)       // 61440

// MODE 0: A = Ain (x), scatter to g_q/g_k/g_v (+bias, q scaled).
// MODE 1: A = g_ctx (device-side symbol! NOT passable from host), dense out.
template<int MODE>
__global__ __launch_bounds__(256) void gemm_mma_kernel(
    const float* __restrict__ Ain,
    const float* __restrict__ B,
    const float* __restrict__ bias,
    float* __restrict__ Cout)
{
    // CRITICAL: g_ctx must be resolved in DEVICE code. Host code passing the
    // __device__ symbol passes the host shadow address (ATS reads zeros).
    const float* __restrict__ A = (MODE == 1) ? (const float*)g_ctx : Ain;

    extern __shared__ char smem[];
    const uint32_t sb = smem_to_u32(smem);
    const int tid = threadIdx.x;
    const int wid = tid >> 5;
    const int lane = tid & 31;
    const int m0 = blockIdx.y * TM;
    const int n0 = blockIdx.x * TN;
    const int wm = wid & 1;
    const int wn = wid >> 1;
    const int g = lane >> 2;        // group 0..7
    const int t = lane & 3;         // thread-in-group

    float acc[4][2][4];
#pragma unroll
    for (int i = 0; i < 4; i++)
#pragma unroll
        for (int j = 0; j < 2; j++)
#pragma unroll
            for (int k = 0; k < 4; k++) acc[i][j][k] = 0.f;

    float4 la[4], lb[2];

    // per-thread fragment base byte offsets (within a stage)
    const uint32_t aoff = (uint32_t)(((wm * 64 + g) * ROWSTR + 2 * t) * 2);
    const uint32_t boff = (uint32_t)(2 * A_HALF + ((wn * 16 + g) * ROWSTR + 2 * t) * 2);

    // ---- chunk 0: load + store to stage 0 ----
    {
#pragma unroll
        for (int i = 0; i < 4; i++) {
            const int v = tid + 256 * i;
            la[i] = *(const float4*)&A[(size_t)(m0 + (v >> 3)) * CDIM + (v & 7) * 4];
        }
#pragma unroll
        for (int i = 0; i < 2; i++) {
            const int v = tid + 256 * i;
            lb[i] = *(const float4*)&B[(size_t)(n0 + (v >> 3)) * CDIM + (v & 7) * 4];
        }
#pragma unroll
        for (int i = 0; i < 4; i++) {
            const int v = tid + 256 * i;
            const uint32_t off = (uint32_t)((v >> 3) * ROWSTR + (v & 7) * 4) * 2;
            split_sts(la[i], sb + off, sb + A_HALF + off);
        }
#pragma unroll
        for (int i = 0; i < 2; i++) {
            const int v = tid + 256 * i;
            const uint32_t off = (uint32_t)((v >> 3) * ROWSTR + (v & 7) * 4) * 2;
            split_sts(lb[i], sb + 2 * A_HALF + off, sb + 2 * A_HALF + B_HALF + off);
        }
    }
    __syncthreads();

    for (int c = 0; c < NCH; c++) {
        if (c + 1 < NCH) {
            const int k0 = (c + 1) * KCH;
#pragma unroll
            for (int i = 0; i < 4; i++) {
                const int v = tid + 256 * i;
                la[i] = *(const float4*)&A[(size_t)(m0 + (v >> 3)) * CDIM + k0 + (v & 7) * 4];
            }
#pragma unroll
            for (int i = 0; i < 2; i++) {
                const int v = tid + 256 * i;
                lb[i] = *(const float4*)&B[(size_t)(n0 + (v >> 3)) * CDIM + k0 + (v & 7) * 4];
            }
        }

        // ---- compute on stage c&1 with explicit per-spec fragment loads ----
        {
            const uint32_t stb = sb + (uint32_t)(c & 1) * STAGE;
            const uint32_t aB = stb + aoff;
            const uint32_t bB = stb + boff;
#pragma unroll
            for (int kk = 0; kk < 2; kk++) {
                // B fragments: b0 = {B[k=2t][n], B[k=2t+1][n]}, b1 = k+8
                uint32_t bh[2][2], bl[2][2];
#pragma unroll
                for (int nf = 0; nf < 2; nf++) {
                    const uint32_t b0a = bB + (uint32_t)((nf * 8 * ROWSTR + kk * 16) * 2);
                    bh[nf][0] = lds_u32(b0a);
                    bh[nf][1] = lds_u32(b0a + 16);
                    bl[nf][0] = lds_u32(b0a + B_HALF);
                    bl[nf][1] = lds_u32(b0a + B_HALF + 16);
                }
#pragma unroll
                for (int mf = 0; mf < 4; mf++) {
                    // A fragments: a0=(row g, k 2t..2t+1), a1=row+8, a2=k+8, a3=both
                    const uint32_t a0a = aB + (uint32_t)((mf * 16 * ROWSTR + kk * 16) * 2);
                    uint32_t ah[4], al[4];
                    ah[0] = lds_u32(a0a);
                    ah[1] = lds_u32(a0a + 8 * ROWSTR * 2);
                    ah[2] = lds_u32(a0a + 16);
                    ah[3] = lds_u32(a0a + 8 * ROWSTR * 2 + 16);
                    al[0] = lds_u32(a0a + A_HALF);
                    al[1] = lds_u32(a0a + A_HALF + 8 * ROWSTR * 2);
                    al[2] = lds_u32(a0a + A_HALF + 16);
                    al[3] = lds_u32(a0a + A_HALF + 8 * ROWSTR * 2 + 16);
#pragma unroll
                    for (int nf = 0; nf < 2; nf++) {
                        mma_bf16(acc[mf][nf], ah, bh[nf][0], bh[nf][1]);
                        mma_bf16(acc[mf][nf], ah, bl[nf][0], bl[nf][1]);
                        mma_bf16(acc[mf][nf], al, bh[nf][0], bh[nf][1]);
                    }
                }
            }
        }

        if (c + 1 < NCH) {
            const uint32_t base = sb + (uint32_t)((c + 1) & 1) * STAGE;
#pragma unroll
            for (int i = 0; i < 4; i++) {
                const int v = tid + 256 * i;
                const uint32_t off = (uint32_t)((v >> 3) * ROWSTR + (v & 7) * 4) * 2;
                split_sts(la[i], base + off, base + A_HALF + off);
            }
#pragma unroll
            for (int i = 0; i < 2; i++) {
                const int v = tid + 256 * i;
                const uint32_t off = (uint32_t)((v >> 3) * ROWSTR + (v & 7) * 4) * 2;
                split_sts(lb[i], base + 2 * A_HALF + off, base + 2 * A_HALF + B_HALF + off);
            }
        }
        __syncthreads();
    }

    // ---- epilogue ----
    // C fragment: c0=(row g, col 2t), c1=(g, 2t+1), c2=(g+8, 2t), c3=(g+8, 2t+1)
    const int rbase = m0 + wm * 64;
    const int colw = n0 + wn * 16;

#pragma unroll
    for (int mf = 0; mf < 4; mf++) {
#pragma unroll
        for (int nf = 0; nf < 2; nf++) {
            const int col = colw + nf * 8 + 2 * t;
            const float2 bs = *(const float2*)&bias[col];
            if (MODE == 0) {
                const int three = n0 / CDIM;   // whole CTA within one of q/k/v
                const int colseg = col - three * CDIM;
                const int h = colseg >> 5;
                const int d = colseg & 31;
                float* __restrict__ dst = (three == 0) ? g_q : ((three == 1) ? g_k : g_v);
                const float sc = (three == 0) ? 0.17677669529663687f : 1.0f;
#pragma unroll
                for (int hf = 0; hf < 2; hf++) {
                    const int r = rbase + mf * 16 + g + hf * 8;
                    const int bw = r / NTOK;
                    const int n = r - bw * NTOK;
                    float2 o;
                    o.x = (acc[mf][nf][hf * 2 + 0] + bs.x) * sc;
                    o.y = (acc[mf][nf][hf * 2 + 1] + bs.y) * sc;
                    *(float2*)&dst[(((size_t)bw * NHEAD + h) * NTOK + n) * HD + d] = o;
                }
            } else {
#pragma unroll
                for (int hf = 0; hf < 2; hf++) {
                    const int r = rbase + mf * 16 + g + hf * 8;
                    float2 o;
                    o.x = acc[mf][nf][hf * 2 + 0] + bs.x;
                    o.y = acc[mf][nf][hf * 2 + 1] + bs.y;
                    *(float2*)&Cout[(size_t)r * CDIM + col] = o;
                }
            }
        }
    }
}

// ---------------------------------------------------------------------------
// Attention: one block per (window, head). 256 threads. (unchanged, known-good)
// ---------------------------------------------------------------------------
__global__ __launch_bounds__(256) void attn_kernel(
    const float* __restrict__ mask,
    const float* __restrict__ bias_table,
    const int*   __restrict__ rel_index)
{
    const int bh = blockIdx.x;
    const int b = bh / NHEAD;
    const int h = bh - b * NHEAD;
    const int wmask = b & (NWMASK - 1);

    __shared__ float qs[NTOK * 33];
    __shared__ float ks[NTOK * 33];
    __shared__ float vs[NTOK * 33];
    __shared__ float s[NTOK * 50];

    const float* __restrict__ qg = g_q + (size_t)bh * NTOK * HD;
    const float* __restrict__ kg = g_k + (size_t)bh * NTOK * HD;
    const float* __restrict__ vg = g_v + (size_t)bh * NTOK * HD;

    for (int idx = threadIdx.x; idx < NTOK * HD; idx += 256) {
        const int n = idx >> 5;
        const int d = idx & 31;
        qs[n * 33 + d] = qg[idx];
        ks[n * 33 + d] = kg[idx];
        vs[n * 33 + d] = vg[idx];
    }
    __syncthreads();

    for (int idx = threadIdx.x; idx < NTOK * NTOK; idx += 256) {
        const int i = idx / NTOK;
        const int j = idx - i * NTOK;
        float a = 0.f;
#pragma unroll
        for (int m = 0; m < HD; m++) a += qs[i * 33 + m] * ks[j * 33 + m];
        a += bias_table[rel_index[idx] * NHEAD + h];
        a += mask[((size_t)wmask * NTOK + i) * NTOK + j];
        s[i * 50 + j] = a;
    }
    __syncthreads();

    const int warp = threadIdx.x >> 5;
    const int lane = threadIdx.x & 31;
    for (int i = warp; i < NTOK; i += 8) {
        float v0 = s[i * 50 + lane];
        float v1 = (lane < NTOK - 32) ? s[i * 50 + lane + 32] : -INFINITY;
        float mx = fmaxf(v0, v1);
#pragma unroll
        for (int o = 16; o > 0; o >>= 1)
            mx = fmaxf(mx, __shfl_xor_sync(0xFFFFFFFFu, mx, o));
        float e0 = __expf(v0 - mx);
        float e1 = (lane < NTOK - 32) ? __expf(v1 - mx) : 0.f;
        float sum = e0 + e1;
#pragma unroll
        for (int o = 16; o > 0; o >>= 1)
            sum += __shfl_xor_sync(0xFFFFFFFFu, sum, o);
        const float inv = 1.f / sum;
        s[i * 50 + lane] = e0 * inv;
        if (lane < NTOK - 32) s[i * 50 + lane + 32] = e1 * inv;
    }
    __syncthreads();

    for (int idx = threadIdx.x; idx < NTOK * HD; idx += 256) {
        const int i = idx >> 5;
        const int d = idx & 31;
        float a = 0.f;
#pragma unroll
        for (int j = 0; j < NTOK; j++) a += s[i * 50 + j] * vs[j * 33 + d];
        g_ctx[((size_t)b * NTOK + i) * CDIM + h * HD + d] = a;
    }
}

// ---------------------------------------------------------------------------
// launch
// ---------------------------------------------------------------------------
extern "C" void kernel_launch(void* const* d_in, const int* in_sizes, int n_in,
                              void* d_out, int out_size)
{
    const float* x          = (const float*)d_in[0];
    const float* mask       = (const float*)d_in[1];
    const float* qkv_w      = (const float*)d_in[2];
    const float* qkv_b      = (const float*)d_in[3];
    const float* proj_w     = (const float*)d_in[4];
    const float* proj_b     = (const float*)d_in[5];
    const float* bias_table = (const float*)d_in[6];
    const int*   rel_index  = (const int*)d_in[7];
    float* out = (float*)d_out;

    cudaFuncSetAttribute(gemm_mma_kernel<0>, cudaFuncAttributeMaxDynamicSharedMemorySize, GEMM_SMEM);
    cudaFuncSetAttribute(gemm_mma_kernel<1>, cudaFuncAttributeMaxDynamicSharedMemorySize, GEMM_SMEM);

    // QKV: A = x [TOKENS,384], B = qkv_w [1152,384]
    dim3 g1(QKV_COLS / TN, TOKENS / TM);   // (18, 1568)
    gemm_mma_kernel<0><<<g1, 256, GEMM_SMEM>>>(x, qkv_w, qkv_b, nullptr);

    attn_kernel<<<BWIN * NHEAD, 256>>>(mask, bias_table, rel_index);

    // Proj: A = g_ctx (resolved inside the kernel), B = proj_w [384,384]
    dim3 g2(CDIM / TN, TOKENS / TM);       // (6, 1568)
    gemm_mma_kernel<1><<<g2, 256, GEMM_SMEM>>>(nullptr, proj_w, proj_b, out);
}

// round 6
// speedup vs baseline: 1.9520x; 1.0339x over previous
#include <cuda_runtime.h>
#include <cuda_bf16.h>
#include <math.h>
#include <stdint.h>

// ---------------------------------------------------------------------------
// Problem constants
// ---------------------------------------------------------------------------
#define BWIN   4096
#define NTOK   49
#define CDIM   384
#define NHEAD  12
#define HD     32
#define NWMASK 64
#define TOKENS (BWIN * NTOK)   // 200704
#define QKV_COLS (3 * CDIM)    // 1152

// Scratch
__device__ float g_q[(size_t)BWIN * NHEAD * NTOK * HD];
__device__ float g_k[(size_t)BWIN * NHEAD * NTOK * HD];
__device__ float g_v[(size_t)BWIN * NHEAD * NTOK * HD];
__device__ float g_ctx[(size_t)TOKENS * CDIM];

// ---------------------------------------------------------------------------
// helpers
// ---------------------------------------------------------------------------
__device__ __forceinline__ uint32_t smem_to_u32(const void* smem_ptr) {
    uint32_t addr;
    asm("{ .reg .u64 tmp; cvta.to.shared.u64 tmp, %1; cvt.u32.u64 %0, tmp; }"
        : "=r"(addr) : "l"(smem_ptr));
    return addr;
}

__device__ __forceinline__ void ldsm4(uint32_t r[4], uint32_t addr) {
    asm volatile("ldmatrix.sync.aligned.m8n8.x4.shared.b16 {%0,%1,%2,%3}, [%4];"
        : "=r"(r[0]), "=r"(r[1]), "=r"(r[2]), "=r"(r[3]) : "r"(addr));
}

__device__ __forceinline__ void mma_bf16(float c[4], const uint32_t a[4],
                                         uint32_t b0, uint32_t b1) {
    asm volatile(
        "mma.sync.aligned.m16n8k16.row.col.f32.bf16.bf16.f32 "
        "{%0,%1,%2,%3}, {%4,%5,%6,%7}, {%8,%9}, {%0,%1,%2,%3};"
        : "+f"(c[0]), "+f"(c[1]), "+f"(c[2]), "+f"(c[3])
        : "r"(a[0]), "r"(a[1]), "r"(a[2]), "r"(a[3]), "r"(b0), "r"(b1));
}

// split fp32x4 into hi/lo bf16x4, store 8B each
__device__ __forceinline__ void split_sts(float4 a, uint32_t hi_addr, uint32_t lo_addr)
{
    __nv_bfloat16 h0 = __float2bfloat16(a.x);
    __nv_bfloat16 h1 = __float2bfloat16(a.y);
    __nv_bfloat16 h2 = __float2bfloat16(a.z);
    __nv_bfloat16 h3 = __float2bfloat16(a.w);
    __nv_bfloat16 l0 = __float2bfloat16(a.x - __bfloat162float(h0));
    __nv_bfloat16 l1 = __float2bfloat16(a.y - __bfloat162float(h1));
    __nv_bfloat16 l2 = __float2bfloat16(a.z - __bfloat162float(h2));
    __nv_bfloat16 l3 = __float2bfloat16(a.w - __bfloat162float(h3));
    uint32_t hx = (uint32_t)__bfloat16_as_ushort(h0) | ((uint32_t)__bfloat16_as_ushort(h1) << 16);
    uint32_t hy = (uint32_t)__bfloat16_as_ushort(h2) | ((uint32_t)__bfloat16_as_ushort(h3) << 16);
    uint32_t lx = (uint32_t)__bfloat16_as_ushort(l0) | ((uint32_t)__bfloat16_as_ushort(l1) << 16);
    uint32_t ly = (uint32_t)__bfloat16_as_ushort(l2) | ((uint32_t)__bfloat16_as_ushort(l3) << 16);
    asm volatile("st.shared.v2.u32 [%0], {%1, %2};" :: "r"(hi_addr), "r"(hx), "r"(hy) : "memory");
    asm volatile("st.shared.v2.u32 [%0], {%1, %2};" :: "r"(lo_addr), "r"(lx), "r"(ly) : "memory");
}

// ---------------------------------------------------------------------------
// GEMM config: CTA tile 128(M) x 64(N), K chunks of 32, double-buffered smem.
// 8 warps: wm = wid&1 (M 64 each), wn = wid>>1 (N 16 each). Warp tile 64x16.
// Smem rows padded to 40 bf16 (80B): ldmatrix row-start banks
// {0,20,8,28,16,4,24,12} tile all 32 banks -> conflict-free.
// ---------------------------------------------------------------------------
#define TM 128
#define TN 64
#define KCH 32
#define NCH (CDIM / KCH)            // 12
#define ROWSTR 40
#define A_HALF (TM * ROWSTR * 2)    // 10240
#define B_HALF (TN * ROWSTR * 2)    // 5120
#define STAGE (2 * A_HALF + 2 * B_HALF)  // 30720
#define GEMM_SMEM (2 * STAGE)       // 61440

// MODE 0: A = Ain (x), scatter to g_q/g_k/g_v (+bias, q scaled).
// MODE 1: A = g_ctx (device-side symbol resolution), dense out (+bias).
template<int MODE>
__global__ __launch_bounds__(256) void gemm_mma_kernel(
    const float* __restrict__ Ain,
    const float* __restrict__ B,
    const float* __restrict__ bias,
    float* __restrict__ Cout)
{
    // CRITICAL: g_ctx must be resolved in DEVICE code (host shadow addr reads
    // zeros via ATS if passed as a kernel arg from host).
    const float* __restrict__ A = (MODE == 1) ? (const float*)g_ctx : Ain;

    extern __shared__ char smem[];
    const uint32_t sb = smem_to_u32(smem);
    const int tid = threadIdx.x;
    const int wid = tid >> 5;
    const int lane = tid & 31;
    const int m0 = blockIdx.y * TM;
    const int n0 = blockIdx.x * TN;
    const int wm = wid & 1;
    const int wn = wid >> 1;
    const int g = lane >> 2;
    const int t = lane & 3;

    float acc[4][2][4];
#pragma unroll
    for (int i = 0; i < 4; i++)
#pragma unroll
        for (int j = 0; j < 2; j++)
#pragma unroll
            for (int k = 0; k < 4; k++) acc[i][j][k] = 0.f;

    float4 la[4], lb[2];

    // ldmatrix per-thread base byte offsets (within a stage)
    // A x4: lanes 0-15 -> rows (wm*64 + lane), col 0; lanes 16-31 -> rows, col 8 (k+8)
    const uint32_t aAddrBase =
        ((uint32_t)((wm * 64 + (lane & 15)) * ROWSTR + (lane >> 4) * 8)) * 2;
    // B x4: tile0 n0-7/k0-7, tile1 n0-7/k8-15, tile2 n8-15/k0-7, tile3 n8-15/k8-15
    const uint32_t bAddrBase =
        ((uint32_t)((wn * 16 + (lane & 7) + ((lane >> 4) & 1) * 8) * ROWSTR
                    + ((lane >> 3) & 1) * 8)) * 2;

    // ---- chunk 0: load + split-store to stage 0 ----
    {
#pragma unroll
        for (int i = 0; i < 4; i++) {
            const int v = tid + 256 * i;
            la[i] = *(const float4*)&A[(size_t)(m0 + (v >> 3)) * CDIM + (v & 7) * 4];
        }
#pragma unroll
        for (int i = 0; i < 2; i++) {
            const int v = tid + 256 * i;
            lb[i] = *(const float4*)&B[(size_t)(n0 + (v >> 3)) * CDIM + (v & 7) * 4];
        }
#pragma unroll
        for (int i = 0; i < 4; i++) {
            const int v = tid + 256 * i;
            const uint32_t off = (uint32_t)((v >> 3) * ROWSTR + (v & 7) * 4) * 2;
            split_sts(la[i], sb + off, sb + A_HALF + off);
        }
#pragma unroll
        for (int i = 0; i < 2; i++) {
            const int v = tid + 256 * i;
            const uint32_t off = (uint32_t)((v >> 3) * ROWSTR + (v & 7) * 4) * 2;
            split_sts(lb[i], sb + 2 * A_HALF + off, sb + 2 * A_HALF + B_HALF + off);
        }
    }
    __syncthreads();

    for (int c = 0; c < NCH; c++) {
        if (c + 1 < NCH) {
            const int k0 = (c + 1) * KCH;
#pragma unroll
            for (int i = 0; i < 4; i++) {
                const int v = tid + 256 * i;
                la[i] = *(const float4*)&A[(size_t)(m0 + (v >> 3)) * CDIM + k0 + (v & 7) * 4];
            }
#pragma unroll
            for (int i = 0; i < 2; i++) {
                const int v = tid + 256 * i;
                lb[i] = *(const float4*)&B[(size_t)(n0 + (v >> 3)) * CDIM + k0 + (v & 7) * 4];
            }
        }

        // ---- compute on stage c&1 via ldmatrix ----
        {
            const uint32_t stb = sb + (uint32_t)(c & 1) * STAGE;
#pragma unroll
            for (int kk = 0; kk < 2; kk++) {
                uint32_t bh[4], bl[4];
                const uint32_t baddr = stb + 2 * A_HALF + bAddrBase + kk * 32;
                ldsm4(bh, baddr);
                ldsm4(bl, baddr + B_HALF);
#pragma unroll
                for (int mf = 0; mf < 4; mf++) {
                    uint32_t ah[4], al[4];
                    const uint32_t aaddr = stb + aAddrBase
                        + (uint32_t)(mf * 16 * ROWSTR + kk * 16) * 2;
                    ldsm4(ah, aaddr);
                    ldsm4(al, aaddr + A_HALF);
#pragma unroll
                    for (int nf = 0; nf < 2; nf++) {
                        mma_bf16(acc[mf][nf], ah, bh[nf * 2], bh[nf * 2 + 1]);
                        mma_bf16(acc[mf][nf], ah, bl[nf * 2], bl[nf * 2 + 1]);
                        mma_bf16(acc[mf][nf], al, bh[nf * 2], bh[nf * 2 + 1]);
                    }
                }
            }
        }

        if (c + 1 < NCH) {
            const uint32_t base = sb + (uint32_t)((c + 1) & 1) * STAGE;
#pragma unroll
            for (int i = 0; i < 4; i++) {
                const int v = tid + 256 * i;
                const uint32_t off = (uint32_t)((v >> 3) * ROWSTR + (v & 7) * 4) * 2;
                split_sts(la[i], base + off, base + A_HALF + off);
            }
#pragma unroll
            for (int i = 0; i < 2; i++) {
                const int v = tid + 256 * i;
                const uint32_t off = (uint32_t)((v >> 3) * ROWSTR + (v & 7) * 4) * 2;
                split_sts(lb[i], base + 2 * A_HALF + off, base + 2 * A_HALF + B_HALF + off);
            }
        }
        __syncthreads();
    }

    // ---- epilogue ----
    // C frag: c0=(row g, col 2t), c1=(g, 2t+1), c2=(g+8, 2t), c3=(g+8, 2t+1)
    const int rbase = m0 + wm * 64;
    const int colw = n0 + wn * 16;

#pragma unroll
    for (int mf = 0; mf < 4; mf++) {
#pragma unroll
        for (int nf = 0; nf < 2; nf++) {
            const int col = colw + nf * 8 + 2 * t;
            const float2 bs = *(const float2*)&bias[col];
            if (MODE == 0) {
                const int three = n0 / CDIM;   // whole CTA within one of q/k/v
                const int colseg = col - three * CDIM;
                const int h = colseg >> 5;
                const int d = colseg & 31;
                float* __restrict__ dst = (three == 0) ? g_q : ((three == 1) ? g_k : g_v);
                const float sc = (three == 0) ? 0.17677669529663687f : 1.0f;
#pragma unroll
                for (int hf = 0; hf < 2; hf++) {
                    const int r = rbase + mf * 16 + g + hf * 8;
                    const int bw = r / NTOK;
                    const int n = r - bw * NTOK;
                    float2 o;
                    o.x = (acc[mf][nf][hf * 2 + 0] + bs.x) * sc;
                    o.y = (acc[mf][nf][hf * 2 + 1] + bs.y) * sc;
                    *(float2*)&dst[(((size_t)bw * NHEAD + h) * NTOK + n) * HD + d] = o;
                }
            } else {
#pragma unroll
                for (int hf = 0; hf < 2; hf++) {
                    const int r = rbase + mf * 16 + g + hf * 8;
                    float2 o;
                    o.x = acc[mf][nf][hf * 2 + 0] + bs.x;
                    o.y = acc[mf][nf][hf * 2 + 1] + bs.y;
                    *(float2*)&Cout[(size_t)r * CDIM + col] = o;
                }
            }
        }
    }
}

// ---------------------------------------------------------------------------
// Attention: one block per (window, head). 256 threads. (unchanged, known-good)
// ---------------------------------------------------------------------------
__global__ __launch_bounds__(256) void attn_kernel(
    const float* __restrict__ mask,
    const float* __restrict__ bias_table,
    const int*   __restrict__ rel_index)
{
    const int bh = blockIdx.x;
    const int b = bh / NHEAD;
    const int h = bh - b * NHEAD;
    const int wmask = b & (NWMASK - 1);

    __shared__ float qs[NTOK * 33];
    __shared__ float ks[NTOK * 33];
    __shared__ float vs[NTOK * 33];
    __shared__ float s[NTOK * 50];

    const float* __restrict__ qg = g_q + (size_t)bh * NTOK * HD;
    const float* __restrict__ kg = g_k + (size_t)bh * NTOK * HD;
    const float* __restrict__ vg = g_v + (size_t)bh * NTOK * HD;

    for (int idx = threadIdx.x; idx < NTOK * HD; idx += 256) {
        const int n = idx >> 5;
        const int d = idx & 31;
        qs[n * 33 + d] = qg[idx];
        ks[n * 33 + d] = kg[idx];
        vs[n * 33 + d] = vg[idx];
    }
    __syncthreads();

    for (int idx = threadIdx.x; idx < NTOK * NTOK; idx += 256) {
        const int i = idx / NTOK;
        const int j = idx - i * NTOK;
        float a = 0.f;
#pragma unroll
        for (int m = 0; m < HD; m++) a += qs[i * 33 + m] * ks[j * 33 + m];
        a += bias_table[rel_index[idx] * NHEAD + h];
        a += mask[((size_t)wmask * NTOK + i) * NTOK + j];
        s[i * 50 + j] = a;
    }
    __syncthreads();

    const int warp = threadIdx.x >> 5;
    const int lane = threadIdx.x & 31;
    for (int i = warp; i < NTOK; i += 8) {
        float v0 = s[i * 50 + lane];
        float v1 = (lane < NTOK - 32) ? s[i * 50 + lane + 32] : -INFINITY;
        float mx = fmaxf(v0, v1);
#pragma unroll
        for (int o = 16; o > 0; o >>= 1)
            mx = fmaxf(mx, __shfl_xor_sync(0xFFFFFFFFu, mx, o));
        float e0 = __expf(v0 - mx);
        float e1 = (lane < NTOK - 32) ? __expf(v1 - mx) : 0.f;
        float sum = e0 + e1;
#pragma unroll
        for (int o = 16; o > 0; o >>= 1)
            sum += __shfl_xor_sync(0xFFFFFFFFu, sum, o);
        const float inv = 1.f / sum;
        s[i * 50 + lane] = e0 * inv;
        if (lane < NTOK - 32) s[i * 50 + lane + 32] = e1 * inv;
    }
    __syncthreads();

    for (int idx = threadIdx.x; idx < NTOK * HD; idx += 256) {
        const int i = idx >> 5;
        const int d = idx & 31;
        float a = 0.f;
#pragma unroll
        for (int j = 0; j < NTOK; j++) a += s[i * 50 + j] * vs[j * 33 + d];
        g_ctx[((size_t)b * NTOK + i) * CDIM + h * HD + d] = a;
    }
}

// ---------------------------------------------------------------------------
// launch
// ---------------------------------------------------------------------------
extern "C" void kernel_launch(void* const* d_in, const int* in_sizes, int n_in,
                              void* d_out, int out_size)
{
    const float* x          = (const float*)d_in[0];
    const float* mask       = (const float*)d_in[1];
    const float* qkv_w      = (const float*)d_in[2];
    const float* qkv_b      = (const float*)d_in[3];
    const float* proj_w     = (const float*)d_in[4];
    const float* proj_b     = (const float*)d_in[5];
    const float* bias_table = (const float*)d_in[6];
    const int*   rel_index  = (const int*)d_in[7];
    float* out = (float*)d_out;

    cudaFuncSetAttribute(gemm_mma_kernel<0>, cudaFuncAttributeMaxDynamicSharedMemorySize, GEMM_SMEM);
    cudaFuncSetAttribute(gemm_mma_kernel<1>, cudaFuncAttributeMaxDynamicSharedMemorySize, GEMM_SMEM);

    // QKV: A = x [TOKENS,384], B = qkv_w [1152,384]
    dim3 g1(QKV_COLS / TN, TOKENS / TM);   // (18, 1568)
    gemm_mma_kernel<0><<<g1, 256, GEMM_SMEM>>>(x, qkv_w, qkv_b, nullptr);

    attn_kernel<<<BWIN * NHEAD, 256>>>(mask, bias_table, rel_index);

    // Proj: A = g_ctx (resolved inside the kernel), B = proj_w [384,384]
    dim3 g2(CDIM / TN, TOKENS / TM);       // (6, 1568)
    gemm_mma_kernel<1><<<g2, 256, GEMM_SMEM>>>(nullptr, proj_w, proj_b, out);
}

// round 7
// speedup vs baseline: 2.2243x; 1.1395x over previous
#include <cuda_runtime.h>
#include <cuda_bf16.h>
#include <math.h>
#include <stdint.h>

// ---------------------------------------------------------------------------
// Problem constants
// ---------------------------------------------------------------------------
#define BWIN   4096
#define NTOK   49
#define CDIM   384
#define NHEAD  12
#define HD     32
#define NWMASK 64
#define TOKENS (BWIN * NTOK)   // 200704
#define QKV_COLS (3 * CDIM)    // 1152
#define NN (NTOK * NTOK)       // 2401

// Scratch
__device__ float g_q[(size_t)BWIN * NHEAD * NTOK * HD];
__device__ float g_k[(size_t)BWIN * NHEAD * NTOK * HD];
__device__ float g_v[(size_t)BWIN * NHEAD * NTOK * HD];
__device__ float g_ctx[(size_t)TOKENS * CDIM];
__device__ float g_mb[(size_t)NWMASK * NHEAD * NN];   // mask + gathered bias

// ---------------------------------------------------------------------------
// helpers
// ---------------------------------------------------------------------------
__device__ __forceinline__ uint32_t smem_to_u32(const void* smem_ptr) {
    uint32_t addr;
    asm("{ .reg .u64 tmp; cvta.to.shared.u64 tmp, %1; cvt.u32.u64 %0, tmp; }"
        : "=r"(addr) : "l"(smem_ptr));
    return addr;
}

__device__ __forceinline__ void ldsm4(uint32_t r[4], uint32_t addr) {
    asm volatile("ldmatrix.sync.aligned.m8n8.x4.shared.b16 {%0,%1,%2,%3}, [%4];"
        : "=r"(r[0]), "=r"(r[1]), "=r"(r[2]), "=r"(r[3]) : "r"(addr));
}

__device__ __forceinline__ void mma_bf16(float c[4], const uint32_t a[4],
                                         uint32_t b0, uint32_t b1) {
    asm volatile(
        "mma.sync.aligned.m16n8k16.row.col.f32.bf16.bf16.f32 "
        "{%0,%1,%2,%3}, {%4,%5,%6,%7}, {%8,%9}, {%0,%1,%2,%3};"
        : "+f"(c[0]), "+f"(c[1]), "+f"(c[2]), "+f"(c[3])
        : "r"(a[0]), "r"(a[1]), "r"(a[2]), "r"(a[3]), "r"(b0), "r"(b1));
}

// split fp32x4 into hi/lo bf16x4, store 8B each
__device__ __forceinline__ void split_sts(float4 a, uint32_t hi_addr, uint32_t lo_addr)
{
    __nv_bfloat16 h0 = __float2bfloat16(a.x);
    __nv_bfloat16 h1 = __float2bfloat16(a.y);
    __nv_bfloat16 h2 = __float2bfloat16(a.z);
    __nv_bfloat16 h3 = __float2bfloat16(a.w);
    __nv_bfloat16 l0 = __float2bfloat16(a.x - __bfloat162float(h0));
    __nv_bfloat16 l1 = __float2bfloat16(a.y - __bfloat162float(h1));
    __nv_bfloat16 l2 = __float2bfloat16(a.z - __bfloat162float(h2));
    __nv_bfloat16 l3 = __float2bfloat16(a.w - __bfloat162float(h3));
    uint32_t hx = (uint32_t)__bfloat16_as_ushort(h0) | ((uint32_t)__bfloat16_as_ushort(h1) << 16);
    uint32_t hy = (uint32_t)__bfloat16_as_ushort(h2) | ((uint32_t)__bfloat16_as_ushort(h3) << 16);
    uint32_t lx = (uint32_t)__bfloat16_as_ushort(l0) | ((uint32_t)__bfloat16_as_ushort(l1) << 16);
    uint32_t ly = (uint32_t)__bfloat16_as_ushort(l2) | ((uint32_t)__bfloat16_as_ushort(l3) << 16);
    asm volatile("st.shared.v2.u32 [%0], {%1, %2};" :: "r"(hi_addr), "r"(hx), "r"(hy) : "memory");
    asm volatile("st.shared.v2.u32 [%0], {%1, %2};" :: "r"(lo_addr), "r"(lx), "r"(ly) : "memory");
}

// ---------------------------------------------------------------------------
// GEMM (unchanged from R6, known-good): 128x64 tile, split-bf16 HMMA.
// ---------------------------------------------------------------------------
#define TM 128
#define TN 64
#define KCH 32
#define NCH (CDIM / KCH)            // 12
#define ROWSTR 40
#define A_HALF (TM * ROWSTR * 2)    // 10240
#define B_HALF (TN * ROWSTR * 2)    // 5120
#define STAGE (2 * A_HALF + 2 * B_HALF)  // 30720
#define GEMM_SMEM (2 * STAGE)       // 61440

template<int MODE>
__global__ __launch_bounds__(256) void gemm_mma_kernel(
    const float* __restrict__ Ain,
    const float* __restrict__ B,
    const float* __restrict__ bias,
    float* __restrict__ Cout)
{
    // g_ctx must be resolved in DEVICE code (host shadow addr reads zeros).
    const float* __restrict__ A = (MODE == 1) ? (const float*)g_ctx : Ain;

    extern __shared__ char smem[];
    const uint32_t sb = smem_to_u32(smem);
    const int tid = threadIdx.x;
    const int wid = tid >> 5;
    const int lane = tid & 31;
    const int m0 = blockIdx.y * TM;
    const int n0 = blockIdx.x * TN;
    const int wm = wid & 1;
    const int wn = wid >> 1;
    const int g = lane >> 2;
    const int t = lane & 3;

    float acc[4][2][4];
#pragma unroll
    for (int i = 0; i < 4; i++)
#pragma unroll
        for (int j = 0; j < 2; j++)
#pragma unroll
            for (int k = 0; k < 4; k++) acc[i][j][k] = 0.f;

    float4 la[4], lb[2];

    const uint32_t aAddrBase =
        ((uint32_t)((wm * 64 + (lane & 15)) * ROWSTR + (lane >> 4) * 8)) * 2;
    const uint32_t bAddrBase =
        ((uint32_t)((wn * 16 + (lane & 7) + ((lane >> 4) & 1) * 8) * ROWSTR
                    + ((lane >> 3) & 1) * 8)) * 2;

    {
#pragma unroll
        for (int i = 0; i < 4; i++) {
            const int v = tid + 256 * i;
            la[i] = *(const float4*)&A[(size_t)(m0 + (v >> 3)) * CDIM + (v & 7) * 4];
        }
#pragma unroll
        for (int i = 0; i < 2; i++) {
            const int v = tid + 256 * i;
            lb[i] = *(const float4*)&B[(size_t)(n0 + (v >> 3)) * CDIM + (v & 7) * 4];
        }
#pragma unroll
        for (int i = 0; i < 4; i++) {
            const int v = tid + 256 * i;
            const uint32_t off = (uint32_t)((v >> 3) * ROWSTR + (v & 7) * 4) * 2;
            split_sts(la[i], sb + off, sb + A_HALF + off);
        }
#pragma unroll
        for (int i = 0; i < 2; i++) {
            const int v = tid + 256 * i;
            const uint32_t off = (uint32_t)((v >> 3) * ROWSTR + (v & 7) * 4) * 2;
            split_sts(lb[i], sb + 2 * A_HALF + off, sb + 2 * A_HALF + B_HALF + off);
        }
    }
    __syncthreads();

    for (int c = 0; c < NCH; c++) {
        if (c + 1 < NCH) {
            const int k0 = (c + 1) * KCH;
#pragma unroll
            for (int i = 0; i < 4; i++) {
                const int v = tid + 256 * i;
                la[i] = *(const float4*)&A[(size_t)(m0 + (v >> 3)) * CDIM + k0 + (v & 7) * 4];
            }
#pragma unroll
            for (int i = 0; i < 2; i++) {
                const int v = tid + 256 * i;
                lb[i] = *(const float4*)&B[(size_t)(n0 + (v >> 3)) * CDIM + k0 + (v & 7) * 4];
            }
        }
        {
            const uint32_t stb = sb + (uint32_t)(c & 1) * STAGE;
#pragma unroll
            for (int kk = 0; kk < 2; kk++) {
                uint32_t bh[4], bl[4];
                const uint32_t baddr = stb + 2 * A_HALF + bAddrBase + kk * 32;
                ldsm4(bh, baddr);
                ldsm4(bl, baddr + B_HALF);
#pragma unroll
                for (int mf = 0; mf < 4; mf++) {
                    uint32_t ah[4], al[4];
                    const uint32_t aaddr = stb + aAddrBase
                        + (uint32_t)(mf * 16 * ROWSTR + kk * 16) * 2;
                    ldsm4(ah, aaddr);
                    ldsm4(al, aaddr + A_HALF);
#pragma unroll
                    for (int nf = 0; nf < 2; nf++) {
                        mma_bf16(acc[mf][nf], ah, bh[nf * 2], bh[nf * 2 + 1]);
                        mma_bf16(acc[mf][nf], ah, bl[nf * 2], bl[nf * 2 + 1]);
                        mma_bf16(acc[mf][nf], al, bh[nf * 2], bh[nf * 2 + 1]);
                    }
                }
            }
        }
        if (c + 1 < NCH) {
            const uint32_t base = sb + (uint32_t)((c + 1) & 1) * STAGE;
#pragma unroll
            for (int i = 0; i < 4; i++) {
                const int v = tid + 256 * i;
                const uint32_t off = (uint32_t)((v >> 3) * ROWSTR + (v & 7) * 4) * 2;
                split_sts(la[i], base + off, base + A_HALF + off);
            }
#pragma unroll
            for (int i = 0; i < 2; i++) {
                const int v = tid + 256 * i;
                const uint32_t off = (uint32_t)((v >> 3) * ROWSTR + (v & 7) * 4) * 2;
                split_sts(lb[i], base + 2 * A_HALF + off, base + 2 * A_HALF + B_HALF + off);
            }
        }
        __syncthreads();
    }

    const int rbase = m0 + wm * 64;
    const int colw = n0 + wn * 16;

#pragma unroll
    for (int mf = 0; mf < 4; mf++) {
#pragma unroll
        for (int nf = 0; nf < 2; nf++) {
            const int col = colw + nf * 8 + 2 * t;
            const float2 bs = *(const float2*)&bias[col];
            if (MODE == 0) {
                const int three = n0 / CDIM;
                const int colseg = col - three * CDIM;
                const int h = colseg >> 5;
                const int d = colseg & 31;
                float* __restrict__ dst = (three == 0) ? g_q : ((three == 1) ? g_k : g_v);
                const float sc = (three == 0) ? 0.17677669529663687f : 1.0f;
#pragma unroll
                for (int hf = 0; hf < 2; hf++) {
                    const int r = rbase + mf * 16 + g + hf * 8;
                    const int bw = r / NTOK;
                    const int n = r - bw * NTOK;
                    float2 o;
                    o.x = (acc[mf][nf][hf * 2 + 0] + bs.x) * sc;
                    o.y = (acc[mf][nf][hf * 2 + 1] + bs.y) * sc;
                    *(float2*)&dst[(((size_t)bw * NHEAD + h) * NTOK + n) * HD + d] = o;
                }
            } else {
#pragma unroll
                for (int hf = 0; hf < 2; hf++) {
                    const int r = rbase + mf * 16 + g + hf * 8;
                    float2 o;
                    o.x = acc[mf][nf][hf * 2 + 0] + bs.x;
                    o.y = acc[mf][nf][hf * 2 + 1] + bs.y;
                    *(float2*)&Cout[(size_t)r * CDIM + col] = o;
                }
            }
        }
    }
}

// ---------------------------------------------------------------------------
// Prep: g_mb[w][h][i*49+j] = mask[w][i][j] + bias_table[rel_index[i][j]][h]
// ---------------------------------------------------------------------------
__global__ __launch_bounds__(256) void prep_mb_kernel(
    const float* __restrict__ mask,
    const float* __restrict__ bias_table,
    const int*   __restrict__ rel_index)
{
    const int idx = blockIdx.x * 256 + threadIdx.x;
    if (idx >= NWMASK * NHEAD * NN) return;
    const int ij = idx % NN;
    const int wh = idx / NN;
    const int h = wh % NHEAD;
    const int w = wh / NHEAD;
    g_mb[idx] = mask[(size_t)w * NN + ij] + bias_table[rel_index[ij] * NHEAD + h];
}

// ---------------------------------------------------------------------------
// Attention: one block per (window, head). 256 threads, register-blocked.
// Score: warp owns 4-row i-tile; q broadcast, one k-column read per lane.
// AV:    warp owns 4-row i-tile x 32 d; v row read once per j, s broadcast.
// ---------------------------------------------------------------------------
__global__ __launch_bounds__(256) void attn_kernel(void)
{
    const int bh = blockIdx.x;
    const int b = bh / NHEAD;
    const int h = bh - b * NHEAD;
    const int wmask = b & (NWMASK - 1);

    __shared__ float qs[52 * 33];   // rows 49..51 zeroed
    __shared__ float ks[NTOK * 33];
    __shared__ float vs[NTOK * 33];
    __shared__ float s[52 * 50];    // rows 49..51 zeroed

    const float* __restrict__ qg = g_q + (size_t)bh * NTOK * HD;
    const float* __restrict__ kg = g_k + (size_t)bh * NTOK * HD;
    const float* __restrict__ vg = g_v + (size_t)bh * NTOK * HD;
    const float* __restrict__ mb = g_mb + (size_t)(wmask * NHEAD + h) * NN;

    for (int idx = threadIdx.x; idx < NTOK * HD; idx += 256) {
        const int n = idx >> 5;
        const int d = idx & 31;
        qs[n * 33 + d] = qg[idx];
        ks[n * 33 + d] = kg[idx];
        vs[n * 33 + d] = vg[idx];
    }
    // zero pad rows
    if (threadIdx.x < 99)  qs[49 * 33 + threadIdx.x] = 0.f;
    if (threadIdx.x < 150) s[49 * 50 + threadIdx.x] = 0.f;
    __syncthreads();

    const int warp = threadIdx.x >> 5;
    const int lane = threadIdx.x & 31;

    // ---- scores: 13 i-tiles of 4 rows ----
    for (int it = warp; it < 13; it += 8) {
        const int i0 = it * 4;
        float a0[4] = {0.f, 0.f, 0.f, 0.f};
        float a1[4] = {0.f, 0.f, 0.f, 0.f};
        const int j1ok = (lane < NTOK - 32);
#pragma unroll
        for (int m = 0; m < HD; m++) {
            const float kv0 = ks[lane * 33 + m];
            const float kv1 = j1ok ? ks[(lane + 32) * 33 + m] : 0.f;
#pragma unroll
            for (int r = 0; r < 4; r++) {
                const float qv = qs[(i0 + r) * 33 + m];   // broadcast
                a0[r] += qv * kv0;
                a1[r] += qv * kv1;
            }
        }
#pragma unroll
        for (int r = 0; r < 4; r++) {
            const int i = i0 + r;
            if (i < NTOK) {
                s[i * 50 + lane] = a0[r] + mb[i * NTOK + lane];
                if (j1ok) s[i * 50 + lane + 32] = a1[r] + mb[i * NTOK + lane + 32];
            }
        }
    }
    __syncthreads();

    // ---- softmax: one warp per row ----
    for (int i = warp; i < NTOK; i += 8) {
        float v0 = s[i * 50 + lane];
        float v1 = (lane < NTOK - 32) ? s[i * 50 + lane + 32] : -INFINITY;
        float mx = fmaxf(v0, v1);
#pragma unroll
        for (int o = 16; o > 0; o >>= 1)
            mx = fmaxf(mx, __shfl_xor_sync(0xFFFFFFFFu, mx, o));
        float e0 = __expf(v0 - mx);
        float e1 = (lane < NTOK - 32) ? __expf(v1 - mx) : 0.f;
        float sum = e0 + e1;
#pragma unroll
        for (int o = 16; o > 0; o >>= 1)
            sum += __shfl_xor_sync(0xFFFFFFFFu, sum, o);
        const float inv = 1.f / sum;
        s[i * 50 + lane] = e0 * inv;
        if (lane < NTOK - 32) s[i * 50 + lane + 32] = e1 * inv;
    }
    __syncthreads();

    // ---- AV: 13 i-tiles of 4 rows x 32 d (d = lane) ----
    float* __restrict__ cg = g_ctx + ((size_t)b * NTOK) * CDIM + h * HD;
    for (int it = warp; it < 13; it += 8) {
        const int i0 = it * 4;
        float a[4] = {0.f, 0.f, 0.f, 0.f};
        for (int j = 0; j < NTOK; j++) {
            const float vv = vs[j * 33 + lane];
#pragma unroll
            for (int r = 0; r < 4; r++)
                a[r] += s[(i0 + r) * 50 + j] * vv;   // s broadcast
        }
#pragma unroll
        for (int r = 0; r < 4; r++) {
            const int i = i0 + r;
            if (i < NTOK) cg[(size_t)i * CDIM + lane] = a[r];
        }
    }
}

// ---------------------------------------------------------------------------
// launch
// ---------------------------------------------------------------------------
extern "C" void kernel_launch(void* const* d_in, const int* in_sizes, int n_in,
                              void* d_out, int out_size)
{
    const float* x          = (const float*)d_in[0];
    const float* mask       = (const float*)d_in[1];
    const float* qkv_w      = (const float*)d_in[2];
    const float* qkv_b      = (const float*)d_in[3];
    const float* proj_w     = (const float*)d_in[4];
    const float* proj_b     = (const float*)d_in[5];
    const float* bias_table = (const float*)d_in[6];
    const int*   rel_index  = (const int*)d_in[7];
    float* out = (float*)d_out;

    cudaFuncSetAttribute(gemm_mma_kernel<0>, cudaFuncAttributeMaxDynamicSharedMemorySize, GEMM_SMEM);
    cudaFuncSetAttribute(gemm_mma_kernel<1>, cudaFuncAttributeMaxDynamicSharedMemorySize, GEMM_SMEM);

    // mb precompute (independent of qkv gemm; cheap)
    prep_mb_kernel<<<(NWMASK * NHEAD * NN + 255) / 256, 256>>>(mask, bias_table, rel_index);

    // QKV: A = x [TOKENS,384], B = qkv_w [1152,384]
    dim3 g1(QKV_COLS / TN, TOKENS / TM);   // (18, 1568)
    gemm_mma_kernel<0><<<g1, 256, GEMM_SMEM>>>(x, qkv_w, qkv_b, nullptr);

    attn_kernel<<<BWIN * NHEAD, 256>>>();

    // Proj: A = g_ctx (resolved inside the kernel), B = proj_w [384,384]
    dim3 g2(CDIM / TN, TOKENS / TM);       // (6, 1568)
    gemm_mma_kernel<1><<<g2, 256, GEMM_SMEM>>>(nullptr, proj_w, proj_b, out);
}